// round 1
// baseline (speedup 1.0000x reference)
#include <cuda_runtime.h>
#include <cuda_bf16.h>

// Problem constants (fixed by the reference)
#define BB   2048
#define VV   2048
#define CC   512
#define MM   8
#define HH   16
#define EPSF 1e-6f

__device__ __forceinline__ float tanh_fast(float x) {
    float y;
    asm("tanh.approx.f32 %0, %1;" : "=f"(y) : "f"(x));
    return y;
}
__device__ __forceinline__ float ex2_fast(float x) {
    float y;
    asm("ex2.approx.f32 %0, %1;" : "=f"(y) : "f"(x));
    return y;
}
__device__ __forceinline__ float rcp_fast(float x) {
    float y;
    asm("rcp.approx.f32 %0, %1;" : "=f"(y) : "f"(x));
    return y;
}

// One block per row b (2048 blocks), one thread per channel c (512 threads).
// Row of preds staged in smem: h_m gathers become LDS; columns [512,2048)
// are copied to the output during the staging pass.
__global__ __launch_bounds__(CC, 1) void gradoptim_attn_kernel(
    const float* __restrict__ preds,
    const int*   __restrict__ mask_ids,
    const float* __restrict__ W1,   // (C, 2, H)
    const float* __restrict__ b1,   // (C, H)
    const float* __restrict__ W2,   // (C, H)
    const float* __restrict__ b2,   // (C,)
    float*       __restrict__ out)  // (B, V)
{
    __shared__ float row[VV];

    const int b = blockIdx.x;
    const int c = threadIdx.x;

    // ---- Stage row b into smem; copy the untouched tail straight to out ----
    const float4* src = reinterpret_cast<const float4*>(preds + (size_t)b * VV);
    float4*       dst = reinterpret_cast<float4*>(out + (size_t)b * VV);
    float4 v4 = src[c];                       // 512 threads x 4 floats = 2048
    reinterpret_cast<float4*>(row)[c] = v4;
    if (c >= CC / 4) dst[c] = v4;             // columns [512, 2048) verbatim

    // ---- Per-channel weights (L1-resident across blocks on the same SM) ----
    float w1a[HH], w1b[HH], b1v[HH], w2s[HH];
    {
        const float4* W1p = reinterpret_cast<const float4*>(W1 + (size_t)c * 2 * HH);
        const float4* b1p = reinterpret_cast<const float4*>(b1 + (size_t)c * HH);
        const float4* W2p = reinterpret_cast<const float4*>(W2 + (size_t)c * HH);
        #pragma unroll
        for (int i = 0; i < 4; i++) {
            float4 a = W1p[i];       // W1[c,0,4i..4i+3]
            float4 bq = W1p[4 + i];  // W1[c,1,4i..4i+3]
            float4 bv = b1p[i];
            float4 w2 = W2p[i];
            w1a[4*i+0] = a.x;  w1a[4*i+1] = a.y;  w1a[4*i+2] = a.z;  w1a[4*i+3] = a.w;
            w1b[4*i+0] = bq.x; w1b[4*i+1] = bq.y; w1b[4*i+2] = bq.z; w1b[4*i+3] = bq.w;
            b1v[4*i+0] = bv.x; b1v[4*i+1] = bv.y; b1v[4*i+2] = bv.z; b1v[4*i+3] = bv.w;
            w2s[4*i+0] = w2.x; w2s[4*i+1] = w2.y; w2s[4*i+2] = w2.z; w2s[4*i+3] = w2.w;
        }
    }
    const float b2c = b2[c];

    // ---- Mask indices for this channel ----
    int idx[MM];
    {
        const int4* mi = reinterpret_cast<const int4*>(mask_ids + (size_t)c * MM);
        int4 i0 = mi[0], i1 = mi[1];
        idx[0] = i0.x; idx[1] = i0.y; idx[2] = i0.z; idx[3] = i0.w;
        idx[4] = i1.x; idx[5] = i1.y; idx[6] = i1.z; idx[7] = i1.w;
    }

    __syncthreads();

    const float h_a = row[c];
    float hm[MM];
    #pragma unroll
    for (int m = 0; m < MM; m++) hm[m] = row[idx[m]];

    // u[h] = h_a * W1[c,0,h] + b1[c,h]  (reused across the M loop)
    float u[HH];
    #pragma unroll
    for (int h = 0; h < HH; h++) u[h] = fmaf(h_a, w1a[h], b1v[h]);

    // score[m] = sum_h W2[h] * tanh(u[h] + h_m * W1[c,1,h]) + b2[c]
    float sc[MM];
    #pragma unroll
    for (int m = 0; m < MM; m++) {
        const float x = hm[m];
        float s = 0.0f;
        #pragma unroll
        for (int h = 0; h < HH; h++) {
            s = fmaf(w2s[h], tanh_fast(fmaf(x, w1b[h], u[h])), s);
        }
        sc[m] = s + b2c;
    }

    // softmax over m, weighted sum of h_m
    float mx = sc[0];
    #pragma unroll
    for (int m = 1; m < MM; m++) mx = fmaxf(mx, sc[m]);

    const float LOG2E = 1.4426950408889634f;
    float sum = 0.0f, ws = 0.0f;
    #pragma unroll
    for (int m = 0; m < MM; m++) {
        float e = ex2_fast((sc[m] - mx) * LOG2E);
        sum = sum + e;
        ws  = fmaf(e, hm[m], ws);
    }
    const float weighted = ws * rcp_fast(sum);
    const float corrected = fmaxf(h_a, weighted + EPSF);

    out[(size_t)b * VV + c] = corrected;
}

extern "C" void kernel_launch(void* const* d_in, const int* in_sizes, int n_in,
                              void* d_out, int out_size) {
    (void)in_sizes; (void)n_in; (void)out_size;
    const float* preds    = (const float*)d_in[0];
    // d_in[1] = ground_truth (unused by the reference)
    const int*   mask_ids = (const int*)  d_in[2];
    const float* W1       = (const float*)d_in[3];
    const float* b1       = (const float*)d_in[4];
    const float* W2       = (const float*)d_in[5];
    const float* b2       = (const float*)d_in[6];
    float*       out      = (float*)d_out;

    gradoptim_attn_kernel<<<BB, CC>>>(preds, mask_ids, W1, b1, W2, b2, out);
}

// round 2
// speedup vs baseline: 1.8732x; 1.8732x over previous
#include <cuda_runtime.h>
#include <cuda_bf16.h>

// Problem constants (fixed by the reference)
#define BB   2048
#define VV   2048
#define CC   512
#define MM   8
#define HH   16
#define EPSF 1e-6f
#define NBLK 148   // persistent: one block per SM on B200 (148 SMs)

__device__ __forceinline__ float tanh_fast(float x) {
    float y;
    asm("tanh.approx.f32 %0, %1;" : "=f"(y) : "f"(x));
    return y;
}
__device__ __forceinline__ float ex2_fast(float x) {
    float y;
    asm("ex2.approx.f32 %0, %1;" : "=f"(y) : "f"(x));
    return y;
}
__device__ __forceinline__ float rcp_fast(float x) {
    float y;
    asm("rcp.approx.f32 %0, %1;" : "=f"(y) : "f"(x));
    return y;
}

// Persistent kernel: 148 blocks, 512 threads (thread = channel c).
// Weights/mask/b2 are per-channel and row-invariant -> load into registers
// ONCE per block, then loop over rows b = blockIdx.x + k*148 with a
// double-buffered smem row so the next row's LDG overlaps compute.
__global__ __launch_bounds__(CC, 1) void gradoptim_attn_kernel(
    const float* __restrict__ preds,
    const int*   __restrict__ mask_ids,
    const float* __restrict__ W1,   // (C, 2, H)
    const float* __restrict__ b1,   // (C, H)
    const float* __restrict__ W2,   // (C, H)
    const float* __restrict__ b2,   // (C,)
    float*       __restrict__ out)  // (B, V)
{
    __shared__ float row[2][VV];

    const int c = threadIdx.x;

    // ---- Per-channel weights: loaded exactly once per block ----
    float w1a[HH], w1b[HH], b1v[HH], w2s[HH];
    {
        const float4* W1p = reinterpret_cast<const float4*>(W1 + (size_t)c * 2 * HH);
        const float4* b1p = reinterpret_cast<const float4*>(b1 + (size_t)c * HH);
        const float4* W2p = reinterpret_cast<const float4*>(W2 + (size_t)c * HH);
        #pragma unroll
        for (int i = 0; i < 4; i++) {
            float4 a = W1p[i];       // W1[c,0,4i..4i+3]
            float4 bq = W1p[4 + i];  // W1[c,1,4i..4i+3]
            float4 bv = b1p[i];
            float4 w2 = W2p[i];
            w1a[4*i+0] = a.x;  w1a[4*i+1] = a.y;  w1a[4*i+2] = a.z;  w1a[4*i+3] = a.w;
            w1b[4*i+0] = bq.x; w1b[4*i+1] = bq.y; w1b[4*i+2] = bq.z; w1b[4*i+3] = bq.w;
            b1v[4*i+0] = bv.x; b1v[4*i+1] = bv.y; b1v[4*i+2] = bv.z; b1v[4*i+3] = bv.w;
            w2s[4*i+0] = w2.x; w2s[4*i+1] = w2.y; w2s[4*i+2] = w2.z; w2s[4*i+3] = w2.w;
        }
    }
    const float b2c = b2[c];

    int idx[MM];
    {
        const int4* mi = reinterpret_cast<const int4*>(mask_ids + (size_t)c * MM);
        int4 i0 = mi[0], i1 = mi[1];
        idx[0] = i0.x; idx[1] = i0.y; idx[2] = i0.z; idx[3] = i0.w;
        idx[4] = i1.x; idx[5] = i1.y; idx[6] = i1.z; idx[7] = i1.w;
    }

    const float LOG2E = 1.4426950408889634f;

    int b = blockIdx.x;
    int buf = 0;
    float4 v4;
    if (b < BB) v4 = reinterpret_cast<const float4*>(preds + (size_t)b * VV)[c];

    while (b < BB) {
        // Stage current row into smem; copy untouched tail columns verbatim.
        reinterpret_cast<float4*>(row[buf])[c] = v4;
        if (c >= CC / 4)
            reinterpret_cast<float4*>(out + (size_t)b * VV)[c] = v4;
        __syncthreads();

        // Prefetch next row NOW so the LDG latency hides under compute.
        const int bn = b + NBLK;
        if (bn < BB) v4 = reinterpret_cast<const float4*>(preds + (size_t)bn * VV)[c];

        // ---- Compute ----
        const float h_a = row[buf][c];
        float hm[MM];
        #pragma unroll
        for (int m = 0; m < MM; m++) hm[m] = row[buf][idx[m]];

        float u[HH];
        #pragma unroll
        for (int h = 0; h < HH; h++) u[h] = fmaf(h_a, w1a[h], b1v[h]);

        float sc[MM];
        #pragma unroll
        for (int m = 0; m < MM; m++) {
            const float x = hm[m];
            float s = 0.0f;
            #pragma unroll
            for (int h = 0; h < HH; h++)
                s = fmaf(w2s[h], tanh_fast(fmaf(x, w1b[h], u[h])), s);
            sc[m] = s + b2c;
        }

        float mx = sc[0];
        #pragma unroll
        for (int m = 1; m < MM; m++) mx = fmaxf(mx, sc[m]);

        float sum = 0.0f, ws = 0.0f;
        #pragma unroll
        for (int m = 0; m < MM; m++) {
            float e = ex2_fast((sc[m] - mx) * LOG2E);
            sum = sum + e;
            ws  = fmaf(e, hm[m], ws);
        }
        const float weighted  = ws * rcp_fast(sum);
        const float corrected = fmaxf(h_a, weighted + EPSF);

        out[(size_t)b * VV + c] = corrected;

        buf ^= 1;
        b = bn;
    }
}

extern "C" void kernel_launch(void* const* d_in, const int* in_sizes, int n_in,
                              void* d_out, int out_size) {
    (void)in_sizes; (void)n_in; (void)out_size;
    const float* preds    = (const float*)d_in[0];
    // d_in[1] = ground_truth (unused by the reference)
    const int*   mask_ids = (const int*)  d_in[2];
    const float* W1       = (const float*)d_in[3];
    const float* b1       = (const float*)d_in[4];
    const float* W2       = (const float*)d_in[5];
    const float* b2       = (const float*)d_in[6];
    float*       out      = (float*)d_out;

    gradoptim_attn_kernel<<<NBLK, CC>>>(preds, mask_ids, W1, b1, W2, b2, out);
}